// round 4
// baseline (speedup 1.0000x reference)
#include <cuda_runtime.h>

#define NB 8
#define NN 1000
#define NM 64
#define NG 50
#define NF 128
#define ROWS (NB * NN)

// Scratch for init = features @ W_init  (4 MB, stays L2-resident; gathers hit L2/L1)
__device__ float g_init[ROWS * NF];

__device__ __forceinline__ float fast_tanh(float x) {
    float y;
    asm("tanh.approx.f32 %0, %1;" : "=f"(y) : "f"(x));
    return y;
}

// ---------------------------------------------------------------------------
// Kernel 1: init[r][j] = sum_k features[r][k] * W_init[k][j]   (0.26 GF)
// ---------------------------------------------------------------------------
__global__ __launch_bounds__(256) void init_kernel(const float* __restrict__ features,
                                                   const float* __restrict__ W_init) {
    __shared__ float sf[16][NF];
    const int row0 = blockIdx.x * 16;
    const int tid = threadIdx.x;
    for (int i = tid; i < 16 * NF; i += 256)
        sf[i >> 7][i & 127] = features[row0 * NF + i];
    __syncthreads();

    const int j = tid & 127;
    const int rh = tid >> 7;  // 0..1, each handles 8 rows
    float acc[8] = {0.f, 0.f, 0.f, 0.f, 0.f, 0.f, 0.f, 0.f};
#pragma unroll 4
    for (int k = 0; k < NF; k++) {
        const float w = W_init[k * NF + j];
#pragma unroll
        for (int i = 0; i < 8; i++) acc[i] += sf[rh * 8 + i][k] * w;
    }
#pragma unroll
    for (int i = 0; i < 8; i++)
        g_init[(row0 + rh * 8 + i) * NF + j] = acc[i];
}

// ---------------------------------------------------------------------------
// Kernel 2: fully fused per-(b,n) block.
//   GEMM1 (64x50 @ 50x128, tanh) -> GEMM2 (64x128 @ 128x128) -> gather*filt
//   -> attention scores -> softmax -> weighted agg -> dense(tanh) -> dense
// 256 threads = 8 warps; warp w owns neighbor rows [8w, 8w+8);
// lane l owns output cols [4l, 4l+4) (float4 weight loads).
// ---------------------------------------------------------------------------
__global__ __launch_bounds__(256, 2) void gcn_kernel(
    const float* __restrict__ rbf,
    const int* __restrict__ nbr,           // int32: harness downcasts int64 inputs
    const float* __restrict__ W1, const float* __restrict__ b1,
    const float* __restrict__ W2, const float* __restrict__ b2,
    const float* __restrict__ nbr_w,
    const float* __restrict__ Wo1, const float* __restrict__ bo1,
    const float* __restrict__ Wo2, const float* __restrict__ bo2,
    float* __restrict__ out, float* __restrict__ attn_out) {
    __shared__ float s_h[NM][NF];       // 32 KB: tanh(rbf@W1+b1)
    __shared__ float s_pool[NM * NG];   // 12.5 KB: rbf tile, later part/agg/y1
    __shared__ float s_score[NM];
    __shared__ float s_attn[NM];
    __shared__ int s_idx[NM];

    const int bn = blockIdx.x;          // 0..7999
    const int b = bn / NN;
    const int tid = threadIdx.x;
    const int w = tid >> 5;
    const int lane = tid & 31;
    const int m0 = w * 8;
    const int j0 = lane * 4;

    // ---- prologue: stage rbf[b,n,:,:] (64x50) + neighbor ids ----
    {
        const float4* src = (const float4*)(rbf + (size_t)bn * (NM * NG));
        float4* dst = (float4*)s_pool;
        for (int i = tid; i < (NM * NG) / 4; i += 256) dst[i] = src[i];
        if (tid < NM) {
            // clamp: if the int32-dtype theory is wrong this degrades a crash
            // into a finite rel_err (diagnosable), and is a no-op when valid.
            int idx = nbr[(size_t)bn * NM + tid];
            s_idx[tid] = min(max(idx, 0), NN - 1);
        }
    }
    __syncthreads();

    // ---- GEMM1: h = tanh(rbf @ W1 + b1) ----
    float acc[8][4];
#pragma unroll
    for (int i = 0; i < 8; i++) {
        acc[i][0] = 0.f; acc[i][1] = 0.f; acc[i][2] = 0.f; acc[i][3] = 0.f;
    }
#pragma unroll 2
    for (int k = 0; k < NG; k++) {
        const float4 wv = *(const float4*)(W1 + k * NF + j0);
#pragma unroll
        for (int i = 0; i < 8; i++) {
            const float r = s_pool[(m0 + i) * NG + k];
            acc[i][0] += r * wv.x; acc[i][1] += r * wv.y;
            acc[i][2] += r * wv.z; acc[i][3] += r * wv.w;
        }
    }
    {
        const float4 bv = *(const float4*)(b1 + j0);
#pragma unroll
        for (int i = 0; i < 8; i++) {
            float4 hv;
            hv.x = fast_tanh(acc[i][0] + bv.x);
            hv.y = fast_tanh(acc[i][1] + bv.y);
            hv.z = fast_tanh(acc[i][2] + bv.z);
            hv.w = fast_tanh(acc[i][3] + bv.w);
            *(float4*)&s_h[m0 + i][j0] = hv;
        }
    }
    __syncthreads();

    // ---- GEMM2: filt = h @ W2 + b2;  conv = gather(init) * filt ----
#pragma unroll
    for (int i = 0; i < 8; i++) {
        acc[i][0] = 0.f; acc[i][1] = 0.f; acc[i][2] = 0.f; acc[i][3] = 0.f;
    }
#pragma unroll 2
    for (int k = 0; k < NF; k++) {
        const float4 wv = *(const float4*)(W2 + k * NF + j0);
#pragma unroll
        for (int i = 0; i < 8; i++) {
            const float h = s_h[m0 + i][k];
            acc[i][0] += h * wv.x; acc[i][1] += h * wv.y;
            acc[i][2] += h * wv.z; acc[i][3] += h * wv.w;
        }
    }
    float p[8];
    {
        const float4 bv = *(const float4*)(b2 + j0);
        const float4 nw = *(const float4*)(nbr_w + j0);
#pragma unroll
        for (int i = 0; i < 8; i++) {
            const float4 gv =
                *(const float4*)(g_init + (size_t)(b * NN + s_idx[m0 + i]) * NF + j0);
            acc[i][0] = (acc[i][0] + bv.x) * gv.x;
            acc[i][1] = (acc[i][1] + bv.y) * gv.y;
            acc[i][2] = (acc[i][2] + bv.z) * gv.z;
            acc[i][3] = (acc[i][3] + bv.w) * gv.w;
            p[i] = acc[i][0] * nw.x + acc[i][1] * nw.y +
                   acc[i][2] * nw.z + acc[i][3] * nw.w;
        }
    }
    // scores: reduce p[i] over the 32 lanes (covers all 128 cols)
#pragma unroll
    for (int off = 16; off > 0; off >>= 1) {
#pragma unroll
        for (int i = 0; i < 8; i++) p[i] += __shfl_xor_sync(0xffffffffu, p[i], off);
    }
    if (lane == 0) {
#pragma unroll
        for (int i = 0; i < 8; i++) s_score[m0 + i] = p[i];
    }
    __syncthreads();

    // ---- softmax over M=64 (warp 0) ----
    if (w == 0) {
        float v0 = s_score[lane], v1 = s_score[lane + 32];
        float mx = fmaxf(v0, v1);
#pragma unroll
        for (int off = 16; off > 0; off >>= 1)
            mx = fmaxf(mx, __shfl_xor_sync(0xffffffffu, mx, off));
        float e0 = __expf(v0 - mx), e1 = __expf(v1 - mx);
        float s = e0 + e1;
#pragma unroll
        for (int off = 16; off > 0; off >>= 1)
            s += __shfl_xor_sync(0xffffffffu, s, off);
        const float inv = 1.0f / s;
        const float a0 = e0 * inv, a1 = e1 * inv;
        s_attn[lane] = a0;
        s_attn[lane + 32] = a1;
        if (attn_out != nullptr) {
            attn_out[(size_t)bn * NM + lane] = a0;
            attn_out[(size_t)bn * NM + 32 + lane] = a1;
        }
    }
    __syncthreads();

    // ---- agg[j] = sum_m attn[m] * conv[m][j]  (conv lives in registers) ----
    float pg[4] = {0.f, 0.f, 0.f, 0.f};
#pragma unroll
    for (int i = 0; i < 8; i++) {
        const float a = s_attn[m0 + i];
        pg[0] += a * acc[i][0]; pg[1] += a * acc[i][1];
        pg[2] += a * acc[i][2]; pg[3] += a * acc[i][3];
    }
    float* s_part = s_pool;          // [8][128]   (rbf tile is dead)
    float* s_agg = s_pool + 1024;    // [128]
    float* s_y1 = s_pool + 1152;     // [128]
    *(float4*)&s_part[w * NF + j0] = make_float4(pg[0], pg[1], pg[2], pg[3]);
    __syncthreads();

    if (tid < NF) {
        float a = 0.f;
#pragma unroll
        for (int ww = 0; ww < 8; ww++) a += s_part[ww * NF + tid];
        s_agg[tid] = a;
    }
    __syncthreads();

    // ---- output dense: tanh(agg @ Wo1 + bo1) @ Wo2 + bo2 ----
    if (tid < NF) {
        float a = bo1[tid];
#pragma unroll 4
        for (int k = 0; k < NF; k++) a += s_agg[k] * Wo1[k * NF + tid];
        s_y1[tid] = fast_tanh(a);
    }
    __syncthreads();
    if (out != nullptr && tid < NF) {
        float a = bo2[tid];
#pragma unroll 4
        for (int k = 0; k < NF; k++) a += s_y1[k] * Wo2[k * NF + tid];
        out[(size_t)bn * NF + tid] = a;
    }
}

// ---------------------------------------------------------------------------
extern "C" void kernel_launch(void* const* d_in, const int* in_sizes, int n_in,
                              void* d_out, int out_size) {
    const float* features = (const float*)d_in[0];
    const float* rbf = (const float*)d_in[1];
    const int* nbr = (const int*)d_in[2];   // int64 in reference -> int32 on device
    const float* W_init = (const float*)d_in[3];
    const float* W1 = (const float*)d_in[4];
    const float* b1 = (const float*)d_in[5];
    const float* W2 = (const float*)d_in[6];
    const float* b2 = (const float*)d_in[7];
    const float* nbr_w = (const float*)d_in[8];
    const float* Wo1 = (const float*)d_in[9];
    const float* bo1 = (const float*)d_in[10];
    const float* Wo2 = (const float*)d_in[11];
    const float* bo2 = (const float*)d_in[12];

    // Derive output layout from out_size instead of assuming it.
    //   full tuple concat:  out [ROWS*NF] then attn [ROWS*NM]
    //   out only:           out [ROWS*NF]
    //   attn only:          attn [ROWS*NM]
    const int sz_out = ROWS * NF;       // 1,024,000
    const int sz_attn = ROWS * NM;      //   512,000
    float* out_ptr = nullptr;
    float* attn_ptr = nullptr;
    if (out_size >= sz_out + sz_attn) {
        out_ptr = (float*)d_out;
        attn_ptr = (float*)d_out + sz_out;
    } else if (out_size >= sz_out) {
        out_ptr = (float*)d_out;
    } else {
        attn_ptr = (float*)d_out;
    }

    init_kernel<<<ROWS / 16, 256>>>(features, W_init);
    gcn_kernel<<<ROWS, 256>>>(rbf, nbr, W1, b1, W2, b2, nbr_w,
                              Wo1, bo1, Wo2, bo2, out_ptr, attn_ptr);
}

// round 8
// speedup vs baseline: 1.4453x; 1.4453x over previous
#include <cuda_runtime.h>

#define NB 8
#define NN 1000
#define NM 64
#define NG 50
#define NF 128
#define ROWS (NB * NN)
#define NT 512   // threads per CTA (16 warps, 4 neighbor-rows per warp)

// Scratch for init = features @ W_init  (4 MB, stays L2-resident; gathers hit L2/L1)
__device__ float g_init[ROWS * NF];

__device__ __forceinline__ float fast_tanh(float x) {
    float y;
    asm("tanh.approx.f32 %0, %1;" : "=f"(y) : "f"(x));
    return y;
}

// ---------------------------------------------------------------------------
// Kernel 1: init[r][j] = sum_k features[r][k] * W_init[k][j]   (0.26 GF)
// ---------------------------------------------------------------------------
__global__ __launch_bounds__(256) void init_kernel(const float* __restrict__ features,
                                                   const float* __restrict__ W_init) {
    __shared__ float sf[16][NF];
    const int row0 = blockIdx.x * 16;
    const int tid = threadIdx.x;
    for (int i = tid; i < 16 * NF; i += 256)
        sf[i >> 7][i & 127] = features[row0 * NF + i];
    __syncthreads();

    const int j = tid & 127;
    const int rh = tid >> 7;  // 0..1, each handles 8 rows
    float acc[8] = {0.f, 0.f, 0.f, 0.f, 0.f, 0.f, 0.f, 0.f};
#pragma unroll 4
    for (int k = 0; k < NF; k++) {
        const float w = W_init[k * NF + j];
#pragma unroll
        for (int i = 0; i < 8; i++) acc[i] += sf[rh * 8 + i][k] * w;
    }
#pragma unroll
    for (int i = 0; i < 8; i++)
        g_init[(row0 + rh * 8 + i) * NF + j] = acc[i];
}

// ---------------------------------------------------------------------------
// Kernel 2: fully fused per-(b,n) block.  512 threads = 16 warps.
// Warp w owns neighbor rows [4w, 4w+4); lane l owns cols [4l, 4l+4).
// ---------------------------------------------------------------------------
__global__ __launch_bounds__(NT, 2) void gcn_kernel(
    const float* __restrict__ rbf,
    const int* __restrict__ nbr,
    const float* __restrict__ W1, const float* __restrict__ b1,
    const float* __restrict__ W2, const float* __restrict__ b2,
    const float* __restrict__ nbr_w,
    const float* __restrict__ Wo1, const float* __restrict__ bo1,
    const float* __restrict__ Wo2, const float* __restrict__ bo2,
    float* __restrict__ out, float* __restrict__ attn_out) {
    __shared__ float s_h[NM][NF];       // 32 KB: tanh(rbf@W1+b1)
    __shared__ float s_pool[NM * NG];   // 12.5 KB: rbf tile; later part/agg/y1
    __shared__ float s_score[NM];
    __shared__ float s_attn[NM];
    __shared__ int s_idx[NM];

    const int bn = blockIdx.x;          // 0..7999
    const int b = bn / NN;
    const int tid = threadIdx.x;
    const int w = tid >> 5;             // 0..15
    const int lane = tid & 31;
    const int m0 = w * 4;               // 4 rows per warp
    const int j0 = lane * 4;            // 4 cols per lane

    // ---- prologue: stage rbf[b,n,:,:] (64x50) + neighbor ids ----
    {
        const float4* src = (const float4*)(rbf + (size_t)bn * (NM * NG));
        float4* dst = (float4*)s_pool;
        for (int i = tid; i < (NM * NG) / 4; i += NT) dst[i] = src[i];
        if (tid < NM) {
            int idx = nbr[(size_t)bn * NM + tid];
            s_idx[tid] = min(max(idx, 0), NN - 1);
        }
    }
    __syncthreads();

    // ---- GEMM1: h = tanh(rbf @ W1 + b1) ----
    float acc[4][4];
#pragma unroll
    for (int i = 0; i < 4; i++) {
        acc[i][0] = 0.f; acc[i][1] = 0.f; acc[i][2] = 0.f; acc[i][3] = 0.f;
    }
#pragma unroll 2
    for (int k = 0; k < NG; k++) {
        const float4 wv = *(const float4*)(W1 + k * NF + j0);
#pragma unroll
        for (int i = 0; i < 4; i++) {
            const float r = s_pool[(m0 + i) * NG + k];
            acc[i][0] += r * wv.x; acc[i][1] += r * wv.y;
            acc[i][2] += r * wv.z; acc[i][3] += r * wv.w;
        }
    }
    {
        const float4 bv = *(const float4*)(b1 + j0);
#pragma unroll
        for (int i = 0; i < 4; i++) {
            float4 hv;
            hv.x = fast_tanh(acc[i][0] + bv.x);
            hv.y = fast_tanh(acc[i][1] + bv.y);
            hv.z = fast_tanh(acc[i][2] + bv.z);
            hv.w = fast_tanh(acc[i][3] + bv.w);
            *(float4*)&s_h[m0 + i][j0] = hv;
        }
    }
    __syncthreads();

    // ---- GEMM2: filt = h @ W2 + b2;  conv = gather(init) * filt ----
#pragma unroll
    for (int i = 0; i < 4; i++) {
        acc[i][0] = 0.f; acc[i][1] = 0.f; acc[i][2] = 0.f; acc[i][3] = 0.f;
    }
#pragma unroll 2
    for (int k = 0; k < NF; k++) {
        const float4 wv = *(const float4*)(W2 + k * NF + j0);
#pragma unroll
        for (int i = 0; i < 4; i++) {
            const float h = s_h[m0 + i][k];
            acc[i][0] += h * wv.x; acc[i][1] += h * wv.y;
            acc[i][2] += h * wv.z; acc[i][3] += h * wv.w;
        }
    }
    float p[4];
    {
        const float4 bv = *(const float4*)(b2 + j0);
        const float4 nw = *(const float4*)(nbr_w + j0);
#pragma unroll
        for (int i = 0; i < 4; i++) {
            const float4 gv =
                *(const float4*)(g_init + (size_t)(b * NN + s_idx[m0 + i]) * NF + j0);
            acc[i][0] = (acc[i][0] + bv.x) * gv.x;
            acc[i][1] = (acc[i][1] + bv.y) * gv.y;
            acc[i][2] = (acc[i][2] + bv.z) * gv.z;
            acc[i][3] = (acc[i][3] + bv.w) * gv.w;
            p[i] = acc[i][0] * nw.x + acc[i][1] * nw.y +
                   acc[i][2] * nw.z + acc[i][3] * nw.w;
        }
    }
    // scores: reduce p[i] over 32 lanes (covers all 128 cols)
#pragma unroll
    for (int off = 16; off > 0; off >>= 1) {
#pragma unroll
        for (int i = 0; i < 4; i++) p[i] += __shfl_xor_sync(0xffffffffu, p[i], off);
    }
    if (lane == 0) {
#pragma unroll
        for (int i = 0; i < 4; i++) s_score[m0 + i] = p[i];
    }
    __syncthreads();

    // ---- softmax over M=64 (warp 0) ----
    if (w == 0) {
        float v0 = s_score[lane], v1 = s_score[lane + 32];
        float mx = fmaxf(v0, v1);
#pragma unroll
        for (int off = 16; off > 0; off >>= 1)
            mx = fmaxf(mx, __shfl_xor_sync(0xffffffffu, mx, off));
        float e0 = __expf(v0 - mx), e1 = __expf(v1 - mx);
        float s = e0 + e1;
#pragma unroll
        for (int off = 16; off > 0; off >>= 1)
            s += __shfl_xor_sync(0xffffffffu, s, off);
        const float inv = 1.0f / s;
        const float a0 = e0 * inv, a1 = e1 * inv;
        s_attn[lane] = a0;
        s_attn[lane + 32] = a1;
        if (attn_out != nullptr) {
            attn_out[(size_t)bn * NM + lane] = a0;
            attn_out[(size_t)bn * NM + 32 + lane] = a1;
        }
    }
    __syncthreads();

    // ---- agg[j] = sum_m attn[m] * conv[m][j]  (conv lives in registers) ----
    float pg[4] = {0.f, 0.f, 0.f, 0.f};
#pragma unroll
    for (int i = 0; i < 4; i++) {
        const float a = s_attn[m0 + i];
        pg[0] += a * acc[i][0]; pg[1] += a * acc[i][1];
        pg[2] += a * acc[i][2]; pg[3] += a * acc[i][3];
    }
    float* s_part = s_pool;           // [16][128] = 2048 floats (rbf tile dead)
    float* s_agg = s_pool + 2048;     // [128]
    float* s_y1 = s_pool + 2176;      // [128]
    *(float4*)&s_part[w * NF + j0] = make_float4(pg[0], pg[1], pg[2], pg[3]);
    __syncthreads();

    if (tid < NF) {
        float a = 0.f;
#pragma unroll
        for (int ww = 0; ww < 16; ww++) a += s_part[ww * NF + tid];
        s_agg[tid] = a;
    }
    __syncthreads();

    // ---- output dense 1 (split-K x4): y1 = tanh(agg @ Wo1 + bo1) ----
    {
        const int j = tid & 127;
        const int q = tid >> 7;       // 0..3, k-range [32q, 32q+32)
        float a = 0.f;
#pragma unroll 4
        for (int k = q * 32; k < q * 32 + 32; k++) a += s_agg[k] * Wo1[k * NF + j];
        s_part[q * NF + j] = a;
    }
    __syncthreads();
    if (tid < NF) {
        float a = bo1[tid] + s_part[tid] + s_part[NF + tid] +
                  s_part[2 * NF + tid] + s_part[3 * NF + tid];
        s_y1[tid] = fast_tanh(a);
    }
    __syncthreads();

    // ---- output dense 2 (split-K x4): out = y1 @ Wo2 + bo2 ----
    {
        const int j = tid & 127;
        const int q = tid >> 7;
        float a = 0.f;
#pragma unroll 4
        for (int k = q * 32; k < q * 32 + 32; k++) a += s_y1[k] * Wo2[k * NF + j];
        s_part[q * NF + j] = a;
    }
    __syncthreads();
    if (out != nullptr && tid < NF) {
        float a = bo2[tid] + s_part[tid] + s_part[NF + tid] +
                  s_part[2 * NF + tid] + s_part[3 * NF + tid];
        out[(size_t)bn * NF + tid] = a;
    }
}

// ---------------------------------------------------------------------------
extern "C" void kernel_launch(void* const* d_in, const int* in_sizes, int n_in,
                              void* d_out, int out_size) {
    const float* features = (const float*)d_in[0];
    const float* rbf = (const float*)d_in[1];
    const int* nbr = (const int*)d_in[2];   // int64 in reference -> int32 on device
    const float* W_init = (const float*)d_in[3];
    const float* W1 = (const float*)d_in[4];
    const float* b1 = (const float*)d_in[5];
    const float* W2 = (const float*)d_in[6];
    const float* b2 = (const float*)d_in[7];
    const float* nbr_w = (const float*)d_in[8];
    const float* Wo1 = (const float*)d_in[9];
    const float* bo1 = (const float*)d_in[10];
    const float* Wo2 = (const float*)d_in[11];
    const float* bo2 = (const float*)d_in[12];

    const int sz_out = ROWS * NF;       // 1,024,000
    const int sz_attn = ROWS * NM;      //   512,000
    float* out_ptr = nullptr;
    float* attn_ptr = nullptr;
    if (out_size >= sz_out + sz_attn) {
        out_ptr = (float*)d_out;
        attn_ptr = (float*)d_out + sz_out;
    } else if (out_size >= sz_out) {
        out_ptr = (float*)d_out;
    } else {
        attn_ptr = (float*)d_out;
    }

    init_kernel<<<ROWS / 16, 256>>>(features, W_init);
    gcn_kernel<<<ROWS, NT>>>(rbf, nbr, W1, b1, W2, b2, nbr_w,
                             Wo1, bo1, Wo2, bo2, out_ptr, attn_ptr);
}

// round 9
// speedup vs baseline: 1.4641x; 1.0130x over previous
#include <cuda_runtime.h>

#define NB 8
#define NN 1000
#define NM 64
#define NG 50
#define NGP 52   // padded rbf row stride (16B-aligned rows)
#define NF 128
#define ROWS (NB * NN)
#define NT 256   // 8 warps; warp owns 8 neighbor rows; lane owns 4 cols

// Scratch for init = features @ W_init  (4 MB, stays L2-resident; gathers hit L2/L1)
__device__ float g_init[ROWS * NF];

__device__ __forceinline__ float fast_tanh(float x) {
    float y;
    asm("tanh.approx.f32 %0, %1;" : "=f"(y) : "f"(x));
    return y;
}

// ---------------------------------------------------------------------------
// Kernel 1: init[r][j] = sum_k features[r][k] * W_init[k][j]   (0.26 GF)
// ---------------------------------------------------------------------------
__global__ __launch_bounds__(256) void init_kernel(const float* __restrict__ features,
                                                   const float* __restrict__ W_init) {
    __shared__ float sf[16][NF];
    const int row0 = blockIdx.x * 16;
    const int tid = threadIdx.x;
    for (int i = tid; i < 16 * NF; i += 256)
        sf[i >> 7][i & 127] = features[row0 * NF + i];
    __syncthreads();

    const int j = tid & 127;
    const int rh = tid >> 7;
    float acc[8] = {0.f, 0.f, 0.f, 0.f, 0.f, 0.f, 0.f, 0.f};
#pragma unroll 4
    for (int k = 0; k < NF; k++) {
        const float w = W_init[k * NF + j];
#pragma unroll
        for (int i = 0; i < 8; i++) acc[i] += sf[rh * 8 + i][k] * w;
    }
#pragma unroll
    for (int i = 0; i < 8; i++)
        g_init[(row0 + rh * 8 + i) * NF + j] = acc[i];
}

// ---------------------------------------------------------------------------
// Kernel 2: fused per-(b,n) block.  256 threads = 8 warps.
// Warp w owns rows [8w, 8w+8); lane l owns cols [4l, 4l+4).
// h/rbf broadcasts batched as 128-bit LDS to minimize l1tex wavefronts.
// ---------------------------------------------------------------------------
__global__ __launch_bounds__(NT, 3) void gcn_kernel(
    const float* __restrict__ rbf,
    const int* __restrict__ nbr,
    const float* __restrict__ W1, const float* __restrict__ b1,
    const float* __restrict__ W2, const float* __restrict__ b2,
    const float* __restrict__ nbr_w,
    const float* __restrict__ Wo1, const float* __restrict__ bo1,
    const float* __restrict__ Wo2, const float* __restrict__ bo2,
    float* __restrict__ out, float* __restrict__ attn_out) {
    __shared__ float s_h[NM][NF];        // 32 KB
    __shared__ float s_pool[NM * NGP];   // 13.3 KB: padded rbf; later part/agg/y1
    __shared__ float s_score[NM];
    __shared__ float s_attn[NM];
    __shared__ int s_idx[NM];

    const int bn = blockIdx.x;
    const int b = bn / NN;
    const int tid = threadIdx.x;
    const int w = tid >> 5;              // 0..7
    const int lane = tid & 31;
    const int m0 = w * 8;                // 8 rows per warp
    const int j0 = lane * 4;             // 4 cols per lane

    // ---- prologue: stage rbf (64x50 -> padded 64x52) + neighbor ids ----
    {
        const float* src = rbf + (size_t)bn * (NM * NG);
        for (int i = tid; i < NM * NG; i += NT)
            s_pool[(i / NG) * NGP + (i % NG)] = src[i];
        if (tid < NM) {
            int idx = nbr[(size_t)bn * NM + tid];
            s_idx[tid] = min(max(idx, 0), NN - 1);
        }
    }
    __syncthreads();

    // ---- GEMM1: h = tanh(rbf @ W1 + b1) ----
    float acc[8][4];
#pragma unroll
    for (int i = 0; i < 8; i++) {
        acc[i][0] = 0.f; acc[i][1] = 0.f; acc[i][2] = 0.f; acc[i][3] = 0.f;
    }
    for (int kb = 0; kb < 48; kb += 4) {
        float4 rv[8];
#pragma unroll
        for (int i = 0; i < 8; i++)
            rv[i] = *(const float4*)&s_pool[(m0 + i) * NGP + kb];
#pragma unroll
        for (int dk = 0; dk < 4; dk++) {
            const float4 wv = *(const float4*)(W1 + (kb + dk) * NF + j0);
#pragma unroll
            for (int i = 0; i < 8; i++) {
                const float r = dk == 0 ? rv[i].x : dk == 1 ? rv[i].y
                              : dk == 2 ? rv[i].z : rv[i].w;
                acc[i][0] += r * wv.x; acc[i][1] += r * wv.y;
                acc[i][2] += r * wv.z; acc[i][3] += r * wv.w;
            }
        }
    }
    {   // tail k = 48, 49
        float2 rv2[8];
#pragma unroll
        for (int i = 0; i < 8; i++)
            rv2[i] = *(const float2*)&s_pool[(m0 + i) * NGP + 48];
#pragma unroll
        for (int dk = 0; dk < 2; dk++) {
            const float4 wv = *(const float4*)(W1 + (48 + dk) * NF + j0);
#pragma unroll
            for (int i = 0; i < 8; i++) {
                const float r = dk == 0 ? rv2[i].x : rv2[i].y;
                acc[i][0] += r * wv.x; acc[i][1] += r * wv.y;
                acc[i][2] += r * wv.z; acc[i][3] += r * wv.w;
            }
        }
    }
    {
        const float4 bv = *(const float4*)(b1 + j0);
#pragma unroll
        for (int i = 0; i < 8; i++) {
            float4 hv;
            hv.x = fast_tanh(acc[i][0] + bv.x);
            hv.y = fast_tanh(acc[i][1] + bv.y);
            hv.z = fast_tanh(acc[i][2] + bv.z);
            hv.w = fast_tanh(acc[i][3] + bv.w);
            *(float4*)&s_h[m0 + i][j0] = hv;
        }
    }
    __syncthreads();

    // ---- GEMM2: filt = h @ W2 + b2;  conv = gather(init) * filt ----
#pragma unroll
    for (int i = 0; i < 8; i++) {
        acc[i][0] = 0.f; acc[i][1] = 0.f; acc[i][2] = 0.f; acc[i][3] = 0.f;
    }
    for (int kb = 0; kb < NF; kb += 4) {
        float4 hv[8];
#pragma unroll
        for (int i = 0; i < 8; i++)
            hv[i] = *(const float4*)&s_h[m0 + i][kb];
#pragma unroll
        for (int dk = 0; dk < 4; dk++) {
            const float4 wv = *(const float4*)(W2 + (kb + dk) * NF + j0);
#pragma unroll
            for (int i = 0; i < 8; i++) {
                const float h = dk == 0 ? hv[i].x : dk == 1 ? hv[i].y
                              : dk == 2 ? hv[i].z : hv[i].w;
                acc[i][0] += h * wv.x; acc[i][1] += h * wv.y;
                acc[i][2] += h * wv.z; acc[i][3] += h * wv.w;
            }
        }
    }
    float p[8];
    {
        const float4 bv = *(const float4*)(b2 + j0);
        const float4 nw = *(const float4*)(nbr_w + j0);
#pragma unroll
        for (int i = 0; i < 8; i++) {
            const float4 gv =
                *(const float4*)(g_init + (size_t)(b * NN + s_idx[m0 + i]) * NF + j0);
            acc[i][0] = (acc[i][0] + bv.x) * gv.x;
            acc[i][1] = (acc[i][1] + bv.y) * gv.y;
            acc[i][2] = (acc[i][2] + bv.z) * gv.z;
            acc[i][3] = (acc[i][3] + bv.w) * gv.w;
            p[i] = acc[i][0] * nw.x + acc[i][1] * nw.y +
                   acc[i][2] * nw.z + acc[i][3] * nw.w;
        }
    }
#pragma unroll
    for (int off = 16; off > 0; off >>= 1) {
#pragma unroll
        for (int i = 0; i < 8; i++) p[i] += __shfl_xor_sync(0xffffffffu, p[i], off);
    }
    if (lane == 0) {
#pragma unroll
        for (int i = 0; i < 8; i++) s_score[m0 + i] = p[i];
    }
    __syncthreads();

    // ---- softmax over M=64 (warp 0) ----
    if (w == 0) {
        float v0 = s_score[lane], v1 = s_score[lane + 32];
        float mx = fmaxf(v0, v1);
#pragma unroll
        for (int off = 16; off > 0; off >>= 1)
            mx = fmaxf(mx, __shfl_xor_sync(0xffffffffu, mx, off));
        float e0 = __expf(v0 - mx), e1 = __expf(v1 - mx);
        float s = e0 + e1;
#pragma unroll
        for (int off = 16; off > 0; off >>= 1)
            s += __shfl_xor_sync(0xffffffffu, s, off);
        const float inv = 1.0f / s;
        const float a0 = e0 * inv, a1 = e1 * inv;
        s_attn[lane] = a0;
        s_attn[lane + 32] = a1;
        if (attn_out != nullptr) {
            attn_out[(size_t)bn * NM + lane] = a0;
            attn_out[(size_t)bn * NM + 32 + lane] = a1;
        }
    }
    __syncthreads();

    // ---- agg[j] = sum_m attn[m] * conv[m][j] ----
    float pg[4] = {0.f, 0.f, 0.f, 0.f};
#pragma unroll
    for (int i = 0; i < 8; i++) {
        const float a = s_attn[m0 + i];
        pg[0] += a * acc[i][0]; pg[1] += a * acc[i][1];
        pg[2] += a * acc[i][2]; pg[3] += a * acc[i][3];
    }
    float* s_part = s_pool;           // [8][128] = 1024 floats (rbf tile dead)
    float* s_agg = s_pool + 1024;     // [128]
    float* s_y1 = s_pool + 1152;      // [128]
    *(float4*)&s_part[w * NF + j0] = make_float4(pg[0], pg[1], pg[2], pg[3]);
    __syncthreads();

    if (tid < NF) {
        float a = 0.f;
#pragma unroll
        for (int ww = 0; ww < 8; ww++) a += s_part[ww * NF + tid];
        s_agg[tid] = a;
    }
    __syncthreads();

    // ---- output dense 1 (split-K x2): y1 = tanh(agg @ Wo1 + bo1) ----
    {
        const int j = tid & 127;
        const int q = tid >> 7;       // 0..1, k-range [64q, 64q+64)
        float a = 0.f;
#pragma unroll 4
        for (int k = q * 64; k < q * 64 + 64; k++) a += s_agg[k] * Wo1[k * NF + j];
        s_part[q * NF + j] = a;
    }
    __syncthreads();
    if (tid < NF) {
        float a = bo1[tid] + s_part[tid] + s_part[NF + tid];
        s_y1[tid] = fast_tanh(a);
    }
    __syncthreads();

    // ---- output dense 2 (split-K x2): out = y1 @ Wo2 + bo2 ----
    {
        const int j = tid & 127;
        const int q = tid >> 7;
        float a = 0.f;
#pragma unroll 4
        for (int k = q * 64; k < q * 64 + 64; k++) a += s_y1[k] * Wo2[k * NF + j];
        s_part[q * NF + j] = a;
    }
    __syncthreads();
    if (out != nullptr && tid < NF) {
        float a = bo2[tid] + s_part[tid] + s_part[NF + tid];
        out[(size_t)bn * NF + tid] = a;
    }
}

// ---------------------------------------------------------------------------
extern "C" void kernel_launch(void* const* d_in, const int* in_sizes, int n_in,
                              void* d_out, int out_size) {
    const float* features = (const float*)d_in[0];
    const float* rbf = (const float*)d_in[1];
    const int* nbr = (const int*)d_in[2];   // int64 in reference -> int32 on device
    const float* W_init = (const float*)d_in[3];
    const float* W1 = (const float*)d_in[4];
    const float* b1 = (const float*)d_in[5];
    const float* W2 = (const float*)d_in[6];
    const float* b2 = (const float*)d_in[7];
    const float* nbr_w = (const float*)d_in[8];
    const float* Wo1 = (const float*)d_in[9];
    const float* bo1 = (const float*)d_in[10];
    const float* Wo2 = (const float*)d_in[11];
    const float* bo2 = (const float*)d_in[12];

    const int sz_out = ROWS * NF;       // 1,024,000
    const int sz_attn = ROWS * NM;      //   512,000
    float* out_ptr = nullptr;
    float* attn_ptr = nullptr;
    if (out_size >= sz_out + sz_attn) {
        out_ptr = (float*)d_out;
        attn_ptr = (float*)d_out + sz_out;
    } else if (out_size >= sz_out) {
        out_ptr = (float*)d_out;
    } else {
        attn_ptr = (float*)d_out;
    }

    init_kernel<<<ROWS / 16, 256>>>(features, W_init);
    gcn_kernel<<<ROWS, NT>>>(rbf, nbr, W1, b1, W2, b2, nbr_w,
                             Wo1, bo1, Wo2, bo2, out_ptr, attn_ptr);
}

// round 12
// speedup vs baseline: 1.6120x; 1.1011x over previous
#include <cuda_runtime.h>

#define NB 8
#define NN 1000
#define NM 64
#define NG 50
#define NGP 52   // padded rbf row stride (16B-aligned rows)
#define NF 128
#define ROWS (NB * NN)
#define NT 256   // 8 warps; warp owns 8 neighbor rows; lane owns 4 cols

__device__ float g_init[ROWS * NF];

__device__ __forceinline__ float fast_tanh(float x) {
    float y;
    asm("tanh.approx.f32 %0, %1;" : "=f"(y) : "f"(x));
    return y;
}

// ---- packed f32x2 helpers (sm_103a FFMA2 path) ----
__device__ __forceinline__ unsigned long long dup_f32x2(float x) {
    unsigned long long r;
    asm("mov.b64 %0, {%1, %1};" : "=l"(r) : "f"(x));
    return r;
}
__device__ __forceinline__ void fma_f32x2(unsigned long long& d,
                                          unsigned long long a,
                                          unsigned long long b) {
    asm("fma.rn.f32x2 %0, %1, %2, %3;" : "=l"(d) : "l"(a), "l"(b), "l"(d));
}
__device__ __forceinline__ float2 unpack_f32x2(unsigned long long v) {
    float2 f;
    asm("mov.b64 {%0, %1}, %2;" : "=f"(f.x), "=f"(f.y) : "l"(v));
    return f;
}

// ---------------------------------------------------------------------------
// Kernel 1: init = features @ W_init   (0.26 GF)
// ---------------------------------------------------------------------------
__global__ __launch_bounds__(256) void init_kernel(const float* __restrict__ features,
                                                   const float* __restrict__ W_init) {
    __shared__ float sf[16][NF];
    const int row0 = blockIdx.x * 16;
    const int tid = threadIdx.x;
    for (int i = tid; i < 16 * NF; i += 256)
        sf[i >> 7][i & 127] = features[row0 * NF + i];
    __syncthreads();

    const int j = tid & 127;
    const int rh = tid >> 7;
    float acc[8] = {0.f, 0.f, 0.f, 0.f, 0.f, 0.f, 0.f, 0.f};
#pragma unroll 4
    for (int k = 0; k < NF; k++) {
        const float w = W_init[k * NF + j];
#pragma unroll
        for (int i = 0; i < 8; i++) acc[i] += sf[rh * 8 + i][k] * w;
    }
#pragma unroll
    for (int i = 0; i < 8; i++)
        g_init[(row0 + rh * 8 + i) * NF + j] = acc[i];
}

// ---------------------------------------------------------------------------
// Kernel 2: fused per-(b,n) block.  256 threads = 8 warps.
// Packed FFMA2 GEMM loops: acc packed over col-pairs; W rows read as
// ulonglong2 (free); broadcast h duplicated via mov.b64 on the idle ALU pipe.
// ---------------------------------------------------------------------------
__global__ __launch_bounds__(NT, 3) void gcn_kernel(
    const float* __restrict__ rbf,
    const int* __restrict__ nbr,
    const float* __restrict__ W1, const float* __restrict__ b1,
    const float* __restrict__ W2, const float* __restrict__ b2,
    const float* __restrict__ nbr_w,
    const float* __restrict__ Wo1, const float* __restrict__ bo1,
    const float* __restrict__ Wo2, const float* __restrict__ bo2,
    float* __restrict__ out, float* __restrict__ attn_out) {
    __shared__ float s_h[NM][NF];        // 32 KB
    __shared__ float s_pool[NM * NGP];   // 13.3 KB: padded rbf; later part/agg/y1
    __shared__ float s_score[NM];
    __shared__ float s_attn[NM];
    __shared__ int s_idx[NM];

    const int bn = blockIdx.x;
    const int b = bn / NN;
    const int tid = threadIdx.x;
    const int w = tid >> 5;
    const int lane = tid & 31;
    const int m0 = w * 8;
    const int j0 = lane * 4;

    // ---- prologue ----
    {
        const float* src = rbf + (size_t)bn * (NM * NG);
        for (int i = tid; i < NM * NG; i += NT)
            s_pool[(i / NG) * NGP + (i % NG)] = src[i];
        if (tid < NM) {
            int idx = nbr[(size_t)bn * NM + tid];
            s_idx[tid] = min(max(idx, 0), NN - 1);
        }
    }
    __syncthreads();

    // ---- GEMM1: h = tanh(rbf @ W1 + b1), packed ----
    unsigned long long acc2[8][2];
#pragma unroll
    for (int i = 0; i < 8; i++) { acc2[i][0] = 0ull; acc2[i][1] = 0ull; }

    for (int kb = 0; kb < 48; kb += 4) {
        float4 rv[8];
#pragma unroll
        for (int i = 0; i < 8; i++)
            rv[i] = *(const float4*)&s_pool[(m0 + i) * NGP + kb];
#pragma unroll
        for (int dk = 0; dk < 4; dk++) {
            const ulonglong2 wp = *(const ulonglong2*)(W1 + (kb + dk) * NF + j0);
#pragma unroll
            for (int i = 0; i < 8; i++) {
                const float r = dk == 0 ? rv[i].x : dk == 1 ? rv[i].y
                              : dk == 2 ? rv[i].z : rv[i].w;
                const unsigned long long rb = dup_f32x2(r);
                fma_f32x2(acc2[i][0], rb, wp.x);
                fma_f32x2(acc2[i][1], rb, wp.y);
            }
        }
    }
    {   // tail k = 48, 49
        float2 rv2[8];
#pragma unroll
        for (int i = 0; i < 8; i++)
            rv2[i] = *(const float2*)&s_pool[(m0 + i) * NGP + 48];
#pragma unroll
        for (int dk = 0; dk < 2; dk++) {
            const ulonglong2 wp = *(const ulonglong2*)(W1 + (48 + dk) * NF + j0);
#pragma unroll
            for (int i = 0; i < 8; i++) {
                const unsigned long long rb = dup_f32x2(dk == 0 ? rv2[i].x : rv2[i].y);
                fma_f32x2(acc2[i][0], rb, wp.x);
                fma_f32x2(acc2[i][1], rb, wp.y);
            }
        }
    }
    {
        const float4 bv = *(const float4*)(b1 + j0);
#pragma unroll
        for (int i = 0; i < 8; i++) {
            const float2 lo = unpack_f32x2(acc2[i][0]);
            const float2 hi = unpack_f32x2(acc2[i][1]);
            float4 hv;
            hv.x = fast_tanh(lo.x + bv.x);
            hv.y = fast_tanh(lo.y + bv.y);
            hv.z = fast_tanh(hi.x + bv.z);
            hv.w = fast_tanh(hi.y + bv.w);
            *(float4*)&s_h[m0 + i][j0] = hv;
        }
    }
    __syncthreads();

    // ---- GEMM2: filt = h @ W2 + b2, packed;  conv = gather(init) * filt ----
#pragma unroll
    for (int i = 0; i < 8; i++) { acc2[i][0] = 0ull; acc2[i][1] = 0ull; }

    for (int kb = 0; kb < NF; kb += 4) {
        float4 hv[8];
#pragma unroll
        for (int i = 0; i < 8; i++)
            hv[i] = *(const float4*)&s_h[m0 + i][kb];
#pragma unroll
        for (int dk = 0; dk < 4; dk++) {
            const ulonglong2 wp = *(const ulonglong2*)(W2 + (kb + dk) * NF + j0);
#pragma unroll
            for (int i = 0; i < 8; i++) {
                const float h = dk == 0 ? hv[i].x : dk == 1 ? hv[i].y
                              : dk == 2 ? hv[i].z : hv[i].w;
                const unsigned long long hb = dup_f32x2(h);
                fma_f32x2(acc2[i][0], hb, wp.x);
                fma_f32x2(acc2[i][1], hb, wp.y);
            }
        }
    }
    float acc[8][4];
    float p[8];
    {
        const float4 bv = *(const float4*)(b2 + j0);
        const float4 nw = *(const float4*)(nbr_w + j0);
#pragma unroll
        for (int i = 0; i < 8; i++) {
            const float4 gv =
                *(const float4*)(g_init + (size_t)(b * NN + s_idx[m0 + i]) * NF + j0);
            const float2 lo = unpack_f32x2(acc2[i][0]);
            const float2 hi = unpack_f32x2(acc2[i][1]);
            acc[i][0] = (lo.x + bv.x) * gv.x;
            acc[i][1] = (lo.y + bv.y) * gv.y;
            acc[i][2] = (hi.x + bv.z) * gv.z;
            acc[i][3] = (hi.y + bv.w) * gv.w;
            p[i] = acc[i][0] * nw.x + acc[i][1] * nw.y +
                   acc[i][2] * nw.z + acc[i][3] * nw.w;
        }
    }
#pragma unroll
    for (int off = 16; off > 0; off >>= 1) {
#pragma unroll
        for (int i = 0; i < 8; i++) p[i] += __shfl_xor_sync(0xffffffffu, p[i], off);
    }
    if (lane == 0) {
#pragma unroll
        for (int i = 0; i < 8; i++) s_score[m0 + i] = p[i];
    }
    __syncthreads();

    // ---- softmax over M=64 (warp 0) ----
    if (w == 0) {
        float v0 = s_score[lane], v1 = s_score[lane + 32];
        float mx = fmaxf(v0, v1);
#pragma unroll
        for (int off = 16; off > 0; off >>= 1)
            mx = fmaxf(mx, __shfl_xor_sync(0xffffffffu, mx, off));
        float e0 = __expf(v0 - mx), e1 = __expf(v1 - mx);
        float s = e0 + e1;
#pragma unroll
        for (int off = 16; off > 0; off >>= 1)
            s += __shfl_xor_sync(0xffffffffu, s, off);
        const float inv = 1.0f / s;
        const float a0 = e0 * inv, a1 = e1 * inv;
        s_attn[lane] = a0;
        s_attn[lane + 32] = a1;
        if (attn_out != nullptr) {
            attn_out[(size_t)bn * NM + lane] = a0;
            attn_out[(size_t)bn * NM + 32 + lane] = a1;
        }
    }
    __syncthreads();

    // ---- agg[j] = sum_m attn[m] * conv[m][j] ----
    float pg[4] = {0.f, 0.f, 0.f, 0.f};
#pragma unroll
    for (int i = 0; i < 8; i++) {
        const float a = s_attn[m0 + i];
        pg[0] += a * acc[i][0]; pg[1] += a * acc[i][1];
        pg[2] += a * acc[i][2]; pg[3] += a * acc[i][3];
    }
    float* s_part = s_pool;           // [8][128]
    float* s_agg = s_pool + 1024;     // [128]
    float* s_y1 = s_pool + 1152;      // [128]
    *(float4*)&s_part[w * NF + j0] = make_float4(pg[0], pg[1], pg[2], pg[3]);
    __syncthreads();

    if (tid < NF) {
        float a = 0.f;
#pragma unroll
        for (int ww = 0; ww < 8; ww++) a += s_part[ww * NF + tid];
        s_agg[tid] = a;
    }
    __syncthreads();

    // ---- output dense 1 (split-K x2): y1 = tanh(agg @ Wo1 + bo1) ----
    {
        const int j = tid & 127;
        const int q = tid >> 7;
        float a = 0.f;
#pragma unroll 4
        for (int k = q * 64; k < q * 64 + 64; k++) a += s_agg[k] * Wo1[k * NF + j];
        s_part[q * NF + j] = a;
    }
    __syncthreads();
    if (tid < NF) {
        float a = bo1[tid] + s_part[tid] + s_part[NF + tid];
        s_y1[tid] = fast_tanh(a);
    }
    __syncthreads();

    // ---- output dense 2 (split-K x2): out = y1 @ Wo2 + bo2 ----
    {
        const int j = tid & 127;
        const int q = tid >> 7;
        float a = 0.f;
#pragma unroll 4
        for (int k = q * 64; k < q * 64 + 64; k++) a += s_y1[k] * Wo2[k * NF + j];
        s_part[q * NF + j] = a;
    }
    __syncthreads();
    if (out != nullptr && tid < NF) {
        float a = bo2[tid] + s_part[tid] + s_part[NF + tid];
        out[(size_t)bn * NF + tid] = a;
    }
}

// ---------------------------------------------------------------------------
extern "C" void kernel_launch(void* const* d_in, const int* in_sizes, int n_in,
                              void* d_out, int out_size) {
    const float* features = (const float*)d_in[0];
    const float* rbf = (const float*)d_in[1];
    const int* nbr = (const int*)d_in[2];
    const float* W_init = (const float*)d_in[3];
    const float* W1 = (const float*)d_in[4];
    const float* b1 = (const float*)d_in[5];
    const float* W2 = (const float*)d_in[6];
    const float* b2 = (const float*)d_in[7];
    const float* nbr_w = (const float*)d_in[8];
    const float* Wo1 = (const float*)d_in[9];
    const float* bo1 = (const float*)d_in[10];
    const float* Wo2 = (const float*)d_in[11];
    const float* bo2 = (const float*)d_in[12];

    const int sz_out = ROWS * NF;       // 1,024,000
    const int sz_attn = ROWS * NM;      //   512,000
    float* out_ptr = nullptr;
    float* attn_ptr = nullptr;
    if (out_size >= sz_out + sz_attn) {
        out_ptr = (float*)d_out;
        attn_ptr = (float*)d_out + sz_out;
    } else if (out_size >= sz_out) {
        out_ptr = (float*)d_out;
    } else {
        attn_ptr = (float*)d_out;
    }

    init_kernel<<<ROWS / 16, 256>>>(features, W_init);
    gcn_kernel<<<ROWS, NT>>>(rbf, nbr, W1, b1, W2, b2, nbr_w,
                             Wo1, bo1, Wo2, bo2, out_ptr, attn_ptr);
}